// round 4
// baseline (speedup 1.0000x reference)
#include <cuda_runtime.h>
#include <math.h>

// ---------------- problem dims ----------------
#define BB   64
#define TT   64
#define DD   8
#define FF   1024
#define HH   1024
#define CC   22
#define INN  4096
#define NROW (BB*TT)      // 4096
#define G4   (4*HH)       // 4096 (also 4*FF)

// ---------------- scratch (static device allocations are allowed) ----------------
__device__ float g_feats[NROW*FF];
__device__ float g_h[NROW*HH];
__device__ float g_c[NROW*HH];
__device__ float g_gates[(size_t)NROW*G4];
__device__ float g_Wcomb[(size_t)G4*HH];
__device__ float g_bdec0[G4];
__device__ float g_bcomb[G4];
__device__ float g_benc[G4];

// ---------------- f32x2 helpers (Blackwell packed fp32) ----------------
typedef unsigned long long ULL;

__device__ __forceinline__ ULL pk2(float lo, float hi) {
    ULL r;
    asm("mov.b64 %0, {%1, %2};" : "=l"(r) : "f"(lo), "f"(hi));
    return r;
}
__device__ __forceinline__ void fma2(ULL& d, ULL a, ULL b) {
    asm("fma.rn.f32x2 %0, %1, %2, %0;" : "+l"(d) : "l"(a), "l"(b));
}

// ---------------- SGEMM: C[M,N] = act( A@B^T (+ alpha2*A2@B2^T) + bias (+ Cadd) ) ----------------
// BT=true : B is [N,K] row-major ("NT", used for all W^T products)
// BT=false: B is [K,N] row-major ("NN", used for Wih@Wdc)
// EPI: 0 = none, 1 = relu
#define BM 128
#define BN 128
#define BK 16
#define LDS 132   // padded smem row stride (floats); 132*4=528B, 16B-aligned rows

template<bool BT, int EPI>
__global__ __launch_bounds__(256, 2)
void sgemm_kernel(const float* __restrict__ A,  int lda,
                  const float* __restrict__ B,  int ldb,
                  const float* __restrict__ A2, int lda2,
                  const float* __restrict__ B2, int ldb2,
                  int K1, int K2, float alpha2,
                  const float* __restrict__ bias,
                  const float* __restrict__ Cadd, int ldadd,
                  float* __restrict__ C, int ldc)
{
    __shared__ __align__(16) float As[2][BK][LDS];
    __shared__ __align__(16) float Bs[2][BK][LDS];

    const int tid  = threadIdx.x;
    const int warp = tid >> 5;
    const int lane = tid & 31;
    const int wm = warp & 1;        // warp grid 2 (M) x 4 (N)
    const int wn = warp >> 1;
    const int lm = lane >> 2;       // lane grid 8 (M) x 4 (N)
    const int ln = lane & 3;

    const int bm = blockIdx.y * BM;
    const int bn = blockIdx.x * BN;

    const int aoff = wm * 64 + lm * 4;   // within-block row offset (plus +32 for 2nd quad)
    const int boff = wn * 32 + ln * 4;   // within-block col offset (plus +16 for 2nd quad)

    // global->smem loader indices
    const int arow0 = tid >> 2;          // 0..63 (rows; +64 for second half)
    const int ac4   = (tid & 3) * 4;     // k-subcolumn 0,4,8,12
    const int bkr0  = tid >> 5;          // NN: k row 0..7 (+8 for second half)
    const int bc4   = (tid & 31) * 4;    // NN: n column offset

    const int nk1 = K1 / BK;
    const int nk2 = K2 / BK;
    const int nkt = nk1 + nk2;

    ULL acc[8][4];
#pragma unroll
    for (int i = 0; i < 8; i++)
#pragma unroll
        for (int c = 0; c < 4; c++) acc[i][c] = 0ull;

    float4 ra0, ra1, rb0, rb1;

    auto ldg_tile = [&](int kt) {
        const float* Ap; int ldap; const float* Bp; int ldbp; int koff; float al;
        if (kt < nk1) { Ap = A;  ldap = lda;  Bp = B;  ldbp = ldb;  koff = kt * BK;          al = 1.0f;   }
        else          { Ap = A2; ldap = lda2; Bp = B2; ldbp = ldb2; koff = (kt - nk1) * BK;  al = alpha2; }
        ra0 = *(const float4*)(Ap + (size_t)(bm + arow0)      * ldap + koff + ac4);
        ra1 = *(const float4*)(Ap + (size_t)(bm + arow0 + 64) * ldap + koff + ac4);
        if (al != 1.0f) {
            ra0.x *= al; ra0.y *= al; ra0.z *= al; ra0.w *= al;
            ra1.x *= al; ra1.y *= al; ra1.z *= al; ra1.w *= al;
        }
        if (BT) {
            rb0 = *(const float4*)(Bp + (size_t)(bn + arow0)      * ldbp + koff + ac4);
            rb1 = *(const float4*)(Bp + (size_t)(bn + arow0 + 64) * ldbp + koff + ac4);
        } else {
            rb0 = *(const float4*)(Bp + (size_t)(koff + bkr0)     * ldbp + bn + bc4);
            rb1 = *(const float4*)(Bp + (size_t)(koff + bkr0 + 8) * ldbp + bn + bc4);
        }
    };

    auto sts_tile = [&](int s) {
        As[s][ac4 + 0][arow0]      = ra0.x;
        As[s][ac4 + 1][arow0]      = ra0.y;
        As[s][ac4 + 2][arow0]      = ra0.z;
        As[s][ac4 + 3][arow0]      = ra0.w;
        As[s][ac4 + 0][arow0 + 64] = ra1.x;
        As[s][ac4 + 1][arow0 + 64] = ra1.y;
        As[s][ac4 + 2][arow0 + 64] = ra1.z;
        As[s][ac4 + 3][arow0 + 64] = ra1.w;
        if (BT) {
            Bs[s][ac4 + 0][arow0]      = rb0.x;
            Bs[s][ac4 + 1][arow0]      = rb0.y;
            Bs[s][ac4 + 2][arow0]      = rb0.z;
            Bs[s][ac4 + 3][arow0]      = rb0.w;
            Bs[s][ac4 + 0][arow0 + 64] = rb1.x;
            Bs[s][ac4 + 1][arow0 + 64] = rb1.y;
            Bs[s][ac4 + 2][arow0 + 64] = rb1.z;
            Bs[s][ac4 + 3][arow0 + 64] = rb1.w;
        } else {
            *(float4*)&Bs[s][bkr0][bc4]     = rb0;
            *(float4*)&Bs[s][bkr0 + 8][bc4] = rb1;
        }
    };

    auto compute = [&](int s) {
#pragma unroll
        for (int k = 0; k < BK; k++) {
            float4 a0 = *(const float4*)&As[s][k][aoff];
            float4 a1 = *(const float4*)&As[s][k][aoff + 32];
            ulonglong2 b0 = *(const ulonglong2*)&Bs[s][k][boff];
            ulonglong2 b1 = *(const ulonglong2*)&Bs[s][k][boff + 16];
            float av[8] = {a0.x, a0.y, a0.z, a0.w, a1.x, a1.y, a1.z, a1.w};
#pragma unroll
            for (int i = 0; i < 8; i++) {
                ULL ad = pk2(av[i], av[i]);
                fma2(acc[i][0], ad, b0.x);
                fma2(acc[i][1], ad, b0.y);
                fma2(acc[i][2], ad, b1.x);
                fma2(acc[i][3], ad, b1.y);
            }
        }
    };

    ldg_tile(0);
    sts_tile(0);
    __syncthreads();

    int s = 0;
    for (int kt = 0; kt < nkt; kt++) {
        const bool pf = (kt + 1) < nkt;
        if (pf) ldg_tile(kt + 1);
        compute(s);
        if (pf) sts_tile(s ^ 1);
        __syncthreads();
        s ^= 1;
    }

    // epilogue
#pragma unroll
    for (int i = 0; i < 8; i++) {
        const int r = bm + aoff + (i < 4 ? i : 28 + i);   // second quad is +32
        float* crow = C + (size_t)r * ldc;
#pragma unroll
        for (int ch = 0; ch < 2; ch++) {
            const int cb = bn + boff + ch * 16;
            float2 p0 = *(float2*)&acc[i][ch * 2 + 0];
            float2 p1 = *(float2*)&acc[i][ch * 2 + 1];
            float4 v = make_float4(p0.x, p0.y, p1.x, p1.y);
            if (bias) {
                const float4 bv = *(const float4*)(bias + cb);
                v.x += bv.x; v.y += bv.y; v.z += bv.z; v.w += bv.w;
            }
            if (Cadd) {
                const float4 av2 = *(const float4*)(Cadd + (size_t)r * ldadd + cb);
                v.x += av2.x; v.y += av2.y; v.z += av2.z; v.w += av2.w;
            }
            if (EPI == 1) {
                v.x = fmaxf(v.x, 0.f); v.y = fmaxf(v.y, 0.f);
                v.z = fmaxf(v.z, 0.f); v.w = fmaxf(v.w, 0.f);
            }
            *(float4*)&crow[cb] = v;
        }
    }
}

// ---------------- LSTM pointwise ----------------
__device__ __forceinline__ float sigm(float x) { return 1.0f / (1.0f + expf(-x)); }

__global__ void lstm_kernel(const float* __restrict__ gates,
                            const float* __restrict__ cprev,   // null => zeros
                            float* __restrict__ h, float* __restrict__ c)
{
    const int idx = blockIdx.x * blockDim.x + threadIdx.x;     // over NROW*HH/4
    const int n  = idx >> 8;                                   // HH/4 = 256
    const int j4 = idx & 255;
    const float4* gp = (const float4*)(gates + (size_t)n * G4);
    const float4 gi = gp[j4];
    const float4 gf = gp[256 + j4];
    const float4 gg = gp[512 + j4];
    const float4 go = gp[768 + j4];
    float4 cp = make_float4(0.f, 0.f, 0.f, 0.f);
    if (cprev) cp = ((const float4*)cprev)[idx];
    float4 cn, hn;
    cn.x = sigm(gf.x) * cp.x + sigm(gi.x) * tanhf(gg.x);  hn.x = sigm(go.x) * tanhf(cn.x);
    cn.y = sigm(gf.y) * cp.y + sigm(gi.y) * tanhf(gg.y);  hn.y = sigm(go.y) * tanhf(cn.y);
    cn.z = sigm(gf.z) * cp.z + sigm(gi.z) * tanhf(gg.z);  hn.z = sigm(go.z) * tanhf(cn.z);
    cn.w = sigm(gf.w) * cp.w + sigm(gi.w) * tanhf(gg.w);  hn.w = sigm(go.w) * tanhf(cn.w);
    ((float4*)c)[idx] = cn;
    ((float4*)h)[idx] = hn;
}

// ---------------- bias prep: bdec0 = bih+bhh; bcomb = bdec0 + Wih@bdc; benc = ebih+ebhh ----------------
__global__ void prep_kernel(const float* __restrict__ dWih, const float* __restrict__ bdc,
                            const float* __restrict__ dbih, const float* __restrict__ dbhh,
                            const float* __restrict__ ebih, const float* __restrict__ ebhh,
                            float* __restrict__ bdec0, float* __restrict__ bcomb,
                            float* __restrict__ benc)
{
    const int g = blockIdx.x;       // 0..G4-1
    const int t = threadIdx.x;      // 128 threads
    float p = 0.f;
    for (int k = t; k < FF; k += 128) p += dWih[(size_t)g * FF + k] * bdc[k];
    p += __shfl_down_sync(0xffffffffu, p, 16);
    p += __shfl_down_sync(0xffffffffu, p, 8);
    p += __shfl_down_sync(0xffffffffu, p, 4);
    p += __shfl_down_sync(0xffffffffu, p, 2);
    p += __shfl_down_sync(0xffffffffu, p, 1);
    __shared__ float sred[4];
    if ((t & 31) == 0) sred[t >> 5] = p;
    __syncthreads();
    if (t == 0) {
        const float srow = sred[0] + sred[1] + sred[2] + sred[3];
        const float b0 = dbih[g] + dbhh[g];
        bdec0[g] = b0;
        bcomb[g] = b0 + srow;
        benc[g]  = ebih[g] + ebhh[g];
    }
}

// ---------------- skinny head: enc_scores[N,22] = h @ Wec^T + bec ----------------
__global__ void encscore_kernel(const float* __restrict__ h, const float* __restrict__ Wec,
                                const float* __restrict__ bec, float* __restrict__ out)
{
    const int warp = threadIdx.x >> 5;
    const int lane = threadIdx.x & 31;
    const int r = blockIdx.x * 8 + warp;   // grid = NROW/8
    float acc[CC];
#pragma unroll
    for (int n = 0; n < CC; n++) acc[n] = 0.f;
    const float* hr = h + (size_t)r * FF;
    for (int u = 0; u < FF / 32; u++) {
        const float hv = hr[u * 32 + lane];
#pragma unroll
        for (int n = 0; n < CC; n++) acc[n] += hv * Wec[n * FF + u * 32 + lane];
    }
#pragma unroll
    for (int n = 0; n < CC; n++) {
        float v = acc[n];
        v += __shfl_xor_sync(0xffffffffu, v, 16);
        v += __shfl_xor_sync(0xffffffffu, v, 8);
        v += __shfl_xor_sync(0xffffffffu, v, 4);
        v += __shfl_xor_sync(0xffffffffu, v, 2);
        v += __shfl_xor_sync(0xffffffffu, v, 1);
        if (lane == 0) out[(size_t)r * CC + n] = v + bec[n];
    }
}

// ---------------- launch ----------------
extern "C" void kernel_launch(void* const* d_in, const int* in_sizes, int n_in,
                              void* d_out, int out_size)
{
    const float* x    = (const float*)d_in[0];
    const float* Wf   = (const float*)d_in[1];
    const float* bf   = (const float*)d_in[2];
    const float* dWih = (const float*)d_in[3];
    const float* dWhh = (const float*)d_in[4];
    const float* dbih = (const float*)d_in[5];
    const float* dbhh = (const float*)d_in[6];
    const float* Wdc  = (const float*)d_in[7];
    const float* bdc  = (const float*)d_in[8];
    const float* eWih = (const float*)d_in[9];
    const float* eWhh = (const float*)d_in[10];
    const float* ebih = (const float*)d_in[11];
    const float* ebhh = (const float*)d_in[12];
    const float* Wec  = (const float*)d_in[13];
    const float* bec  = (const float*)d_in[14];

    float* enc_out = (float*)d_out;                              // [NROW, 22]
    float* dec_out = (float*)d_out + (size_t)NROW * CC;          // [NROW, D, F]

    float *feats, *hbuf, *cbuf, *gates, *Wcomb, *bdec0, *bcomb, *benc;
    cudaGetSymbolAddress((void**)&feats, g_feats);
    cudaGetSymbolAddress((void**)&hbuf,  g_h);
    cudaGetSymbolAddress((void**)&cbuf,  g_c);
    cudaGetSymbolAddress((void**)&gates, g_gates);
    cudaGetSymbolAddress((void**)&Wcomb, g_Wcomb);
    cudaGetSymbolAddress((void**)&bdec0, g_bdec0);
    cudaGetSymbolAddress((void**)&bcomb, g_bcomb);
    cudaGetSymbolAddress((void**)&benc,  g_benc);

    const dim3 gridBig(G4 / BN, NROW / BM);    // 32 x 32  (gates GEMMs)
    const dim3 gridOut(FF / BN, NROW / BM);    // 8  x 32  (out/feats/Wcomb GEMMs)
    const int  lstmGrid = NROW * HH / 4 / 256; // 4096

    // 1) feats = relu(x @ Wf^T + bf)        [NROW, FF], K=INN
    sgemm_kernel<true, 1><<<gridOut, 256>>>(x, INN, Wf, INN,
                                            nullptr, 0, nullptr, 0, INN, 0, 1.f,
                                            bf, nullptr, 0, feats, FF);

    // 2) Wcomb = dWih @ Wdc + dWhh          [G4, HH], K=FF   (NN)
    sgemm_kernel<false, 0><<<gridOut, 256>>>(dWih, FF, Wdc, HH,
                                             nullptr, 0, nullptr, 0, FF, 0, 1.f,
                                             nullptr, dWhh, HH, Wcomb, HH);

    // 3) bias prep
    prep_kernel<<<G4, 128>>>(dWih, bdc, dbih, dbhh, ebih, ebhh, bdec0, bcomb, benc);

    // 4) decoder step 0 (h0 = c0 = 0 -> gates = feats @ dWih^T + bih + bhh)
    sgemm_kernel<true, 0><<<gridBig, 256>>>(feats, FF, dWih, FF,
                                            nullptr, 0, nullptr, 0, FF, 0, 1.f,
                                            bdec0, nullptr, 0, gates, G4);
    lstm_kernel<<<lstmGrid, 256>>>(gates, nullptr, hbuf, cbuf);
    sgemm_kernel<true, 0><<<gridOut, 256>>>(hbuf, HH, Wdc, HH,
                                            nullptr, 0, nullptr, 0, HH, 0, 1.f,
                                            bdc, nullptr, 0, dec_out + 0 * FF, DD * FF);

    // 5) decoder steps 1..7: gates = h @ Wcomb^T + bcomb
    for (int t = 1; t < DD; t++) {
        sgemm_kernel<true, 0><<<gridBig, 256>>>(hbuf, HH, Wcomb, HH,
                                                nullptr, 0, nullptr, 0, HH, 0, 1.f,
                                                bcomb, nullptr, 0, gates, G4);
        lstm_kernel<<<lstmGrid, 256>>>(gates, cbuf, hbuf, cbuf);
        sgemm_kernel<true, 0><<<gridOut, 256>>>(hbuf, HH, Wdc, HH,
                                                nullptr, 0, nullptr, 0, HH, 0, 1.f,
                                                bdc, nullptr, 0, dec_out + t * FF, DD * FF);
    }

    // 6) encoder gates = feats @ eWih^T + (last_out/D) @ eWhh^T + ebih + ebhh
    sgemm_kernel<true, 0><<<gridBig, 256>>>(feats, FF, eWih, FF,
                                            dec_out + (DD - 1) * FF, DD * FF, eWhh, FF,
                                            FF, FF, 1.0f / (float)DD,
                                            benc, nullptr, 0, gates, G4);
    // encoder cell with c0 = 0
    lstm_kernel<<<lstmGrid, 256>>>(gates, nullptr, hbuf, cbuf);

    // 7) enc_scores = enc_h @ Wec^T + bec
    encscore_kernel<<<NROW / 8, 256>>>(hbuf, Wec, bec, enc_out);
}

// round 7
// speedup vs baseline: 2.0753x; 2.0753x over previous
#include <cuda_runtime.h>
#include <cuda_bf16.h>
#include <math.h>
#include <stdint.h>

#define DD   8
#define FF   1024
#define HH   1024
#define CC   22
#define INN  4096
#define NROW 4096
#define G4   4096

typedef __nv_bfloat16 bf16;

// ---------------- arena ----------------
constexpr size_t SZ_X  = (size_t)NROW * INN * 2;
constexpr size_t SZ_W4 = (size_t)G4 * FF * 2;
constexpr size_t SZ_W1 = (size_t)FF * HH * 2;

constexpr size_t O_XH  = 0;
constexpr size_t O_XL  = O_XH + SZ_X;
constexpr size_t O_WFH = O_XL + SZ_X;
constexpr size_t O_WFL = O_WFH + SZ_W4;
constexpr size_t O_DIH = O_WFL + SZ_W4;
constexpr size_t O_DIL = O_DIH + SZ_W4;
constexpr size_t O_EIH = O_DIL + SZ_W4;
constexpr size_t O_EIL = O_EIH + SZ_W4;
constexpr size_t O_EHH = O_EIL + SZ_W4;
constexpr size_t O_EHL = O_EHH + SZ_W4;
constexpr size_t O_WDH = O_EHL + SZ_W4;
constexpr size_t O_WDL = O_WDH + SZ_W1;
constexpr size_t O_WTH = O_WDL + SZ_W1;
constexpr size_t O_WTL = O_WTH + SZ_W1;
constexpr size_t O_WCH = O_WTL + SZ_W1;
constexpr size_t O_WCL = O_WCH + SZ_W4;
constexpr size_t O_FH  = O_WCL + SZ_W4;
constexpr size_t O_FL  = O_FH + SZ_W4;
constexpr size_t O_HH  = O_FL + SZ_W4;
constexpr size_t O_HL  = O_HH + SZ_W4;
constexpr size_t O_LH  = O_HL + SZ_W4;
constexpr size_t O_LL  = O_LH + SZ_W4;
constexpr size_t O_C   = O_LL + SZ_W4;
constexpr size_t O_G   = O_C  + (size_t)NROW * HH * 4;
constexpr size_t O_HF  = O_G  + (size_t)NROW * G4 * 4;
constexpr size_t O_B0  = O_HF + (size_t)NROW * HH * 4;
constexpr size_t O_B1  = O_B0 + (size_t)G4 * 4;
constexpr size_t O_B2  = O_B1 + (size_t)G4 * 4;
constexpr size_t ARENA = O_B2 + (size_t)G4 * 4;

__device__ __align__(1024) unsigned char g_arena[ARENA];

// ---------------- helpers ----------------
__device__ __forceinline__ uint32_t smem_u32(const void* p) {
    uint32_t a;
    asm("{ .reg .u64 t; cvta.to.shared.u64 t, %1; cvt.u32.u64 %0, t; }" : "=r"(a) : "l"(p));
    return a;
}
__device__ __forceinline__ void ldsm4(uint32_t& r0, uint32_t& r1, uint32_t& r2, uint32_t& r3,
                                      uint32_t addr) {
    asm volatile("ldmatrix.sync.aligned.m8n8.x4.shared.b16 {%0,%1,%2,%3}, [%4];"
                 : "=r"(r0), "=r"(r1), "=r"(r2), "=r"(r3) : "r"(addr));
}
__device__ __forceinline__ void mma16816(float* c, const uint32_t* a, const uint32_t* b) {
    asm volatile("mma.sync.aligned.m16n8k16.row.col.f32.bf16.bf16.f32 "
                 "{%0,%1,%2,%3}, {%4,%5,%6,%7}, {%8,%9}, {%0,%1,%2,%3};"
                 : "+f"(c[0]), "+f"(c[1]), "+f"(c[2]), "+f"(c[3])
                 : "r"(a[0]), "r"(a[1]), "r"(a[2]), "r"(a[3]), "r"(b[0]), "r"(b[1]));
}
__device__ __forceinline__ void split2(float v, unsigned short& hi, unsigned short& lo) {
    bf16 h = __float2bfloat16(v);
    bf16 l = __float2bfloat16(v - __bfloat162float(h));
    hi = *(unsigned short*)&h;
    lo = *(unsigned short*)&l;
}

// ---------------- HMMA split-bf16 GEMM ----------------
// C[M,N] = sum_p A_p @ B_p^T ; A_p [M,Kp], B_p [N,Kp] row-major bf16 (K-major).
// CTA tile 128x128; BK=32; 4-stage cp.async pipeline; fp32 accum in registers.
struct Passes { const bf16* A[6]; const bf16* B[6]; };

#define STAGES      4
#define ROWPITCH    80                  // 64B data + 16B pad (conflict-free ldmatrix)
#define A_BYTES     (128 * ROWPITCH)    // 10240
#define STAGE_BYTES (2 * A_BYTES)       // 20480
#define SMEM_DYN    (STAGES * STAGE_BYTES)

__global__ __launch_bounds__(256, 2)
void tcgemm(Passes P, int nPass, int Kp,
            const float* __restrict__ bias,
            const float* __restrict__ Cadd, int ldadd,
            float* __restrict__ Cout, int ldc,
            bf16* __restrict__ Oh, bf16* __restrict__ Ol, int ldo,
            float oscale, int relu)
{
    extern __shared__ __align__(16) unsigned char dsm[];
    const uint32_t sbase = smem_u32(dsm);

    const int tid = threadIdx.x, wid = tid >> 5, lane = tid & 31;
    const int wm = wid >> 2;        // 0..1  (64-row halves)
    const int wn = wid & 3;         // 0..3  (32-col quarters)
    const int tm = blockIdx.y, tn = blockIdx.x;

    const int ck  = Kp >> 5;        // chunks per pass
    const int nkt = nPass * ck;

    // loader indices: thread covers 2 chunks per operand (512 chunks / 256 thr)
    auto load_chunk = [&](int f) {
        const int buf = f & 3;
        const int p = f / ck, ko = (f - p * ck) << 5;
        const bf16* Ag = P.A[p] + (size_t)(tm * 128) * Kp + ko;
        const bf16* Bg = P.B[p] + (size_t)(tn * 128) * Kp + ko;
        const uint32_t sA = sbase + (uint32_t)buf * STAGE_BYTES;
        const uint32_t sB = sA + A_BYTES;
#pragma unroll
        for (int j = 0; j < 2; j++) {
            const int i = tid + 256 * j;
            const int row = i >> 2, ch = i & 3;
            const uint32_t d = (uint32_t)row * ROWPITCH + (uint32_t)ch * 16;
            asm volatile("cp.async.cg.shared.global [%0], [%1], 16;"
                         :: "r"(sA + d), "l"(Ag + (size_t)row * Kp + ch * 8) : "memory");
            asm volatile("cp.async.cg.shared.global [%0], [%1], 16;"
                         :: "r"(sB + d), "l"(Bg + (size_t)row * Kp + ch * 8) : "memory");
        }
        asm volatile("cp.async.commit_group;" ::: "memory");
    };

    float c[4][4][4];
#pragma unroll
    for (int i = 0; i < 4; i++)
#pragma unroll
        for (int j = 0; j < 4; j++)
#pragma unroll
            for (int k = 0; k < 4; k++) c[i][j][k] = 0.f;

    // ldmatrix lane addressing (constant parts)
    const uint32_t a_row = (uint32_t)(wm * 64 + (lane & 15));
    const uint32_t a_ch  = (uint32_t)((lane >> 4) * 16);
    const uint32_t b_row = (uint32_t)(wn * 32 + ((lane >> 4) << 3) + (lane & 7));
    const uint32_t b_ch  = (uint32_t)(((lane >> 3) & 1) * 16);

    // prefetch
    for (int f = 0; f < STAGES - 1 && f < nkt; f++) load_chunk(f);

    for (int kt = 0; kt < nkt; kt++) {
        int w = nkt - kt - 1;
        if (w > STAGES - 2) w = STAGES - 2;
        if (w == 2)      asm volatile("cp.async.wait_group 2;" ::: "memory");
        else if (w == 1) asm volatile("cp.async.wait_group 1;" ::: "memory");
        else             asm volatile("cp.async.wait_group 0;" ::: "memory");
        __syncthreads();

        const int f = kt + STAGES - 1;
        if (f < nkt) load_chunk(f);

        const uint32_t sA = sbase + (uint32_t)(kt & 3) * STAGE_BYTES;
        const uint32_t sB = sA + A_BYTES;
#pragma unroll
        for (int ks = 0; ks < 2; ks++) {
            uint32_t a[4][4], b[4][2];
#pragma unroll
            for (int mf = 0; mf < 4; mf++) {
                const uint32_t addr = sA + (a_row + mf * 16) * ROWPITCH + ks * 32 + a_ch;
                ldsm4(a[mf][0], a[mf][1], a[mf][2], a[mf][3], addr);
            }
#pragma unroll
            for (int np = 0; np < 2; np++) {
                const uint32_t addr = sB + (b_row + np * 16) * ROWPITCH + ks * 32 + b_ch;
                ldsm4(b[2 * np][0], b[2 * np][1], b[2 * np + 1][0], b[2 * np + 1][1], addr);
            }
#pragma unroll
            for (int mf = 0; mf < 4; mf++)
#pragma unroll
                for (int nf = 0; nf < 4; nf++)
                    mma16816(c[mf][nf], a[mf], b[nf]);
        }
    }

    // ---------------- epilogue ----------------
    const int tr = lane >> 2, tc = (lane & 3) * 2;
#pragma unroll
    for (int mf = 0; mf < 4; mf++) {
#pragma unroll
        for (int half = 0; half < 2; half++) {
            const size_t row = (size_t)tm * 128 + wm * 64 + mf * 16 + tr + half * 8;
            float* crow = Cout ? Cout + row * (size_t)ldc : (float*)0;
            const float* arow = Cadd ? Cadd + row * (size_t)ldadd : (const float*)0;
            bf16* ohr = Oh ? Oh + row * (size_t)ldo : (bf16*)0;
            bf16* olr = Ol ? Ol + row * (size_t)ldo : (bf16*)0;
#pragma unroll
            for (int nf = 0; nf < 4; nf++) {
                const int col = tn * 128 + wn * 32 + nf * 8 + tc;
                float vx = c[mf][nf][half * 2 + 0];
                float vy = c[mf][nf][half * 2 + 1];
                if (bias) { vx += bias[col]; vy += bias[col + 1]; }
                if (arow) { vx += arow[col]; vy += arow[col + 1]; }
                if (relu) { vx = fmaxf(vx, 0.f); vy = fmaxf(vy, 0.f); }
                if (crow) { *(float2*)(crow + col) = make_float2(vx, vy); }
                if (ohr) {
                    unsigned short h0, l0, h1, l1;
                    split2(vx * oscale, h0, l0);
                    split2(vy * oscale, h1, l1);
                    *(ushort2*)((unsigned short*)ohr + col) = make_ushort2(h0, h1);
                    *(ushort2*)((unsigned short*)olr + col) = make_ushort2(l0, l1);
                }
            }
        }
    }
}

// ---------------- split fp32 -> (bf16 hi, bf16 lo) ----------------
__global__ void split_kernel(const float* __restrict__ s,
                             bf16* __restrict__ h, bf16* __restrict__ l)
{
    const size_t i = (size_t)blockIdx.x * 256 + threadIdx.x;
    const float4 v = ((const float4*)s)[i];
    unsigned short h0, l0, h1, l1, h2, l2, h3, l3;
    split2(v.x, h0, l0); split2(v.y, h1, l1); split2(v.z, h2, l2); split2(v.w, h3, l3);
    ((ushort4*)h)[i] = make_ushort4(h0, h1, h2, h3);
    ((ushort4*)l)[i] = make_ushort4(l0, l1, l2, l3);
}

// transpose + split: WdcT[h,f] = Wdc[f,h]
__global__ void tsplit_kernel(const float* __restrict__ W,
                              bf16* __restrict__ th, bf16* __restrict__ tl)
{
    __shared__ float t[32][33];
    const int f0 = blockIdx.y * 32, h0 = blockIdx.x * 32;
    t[threadIdx.y][threadIdx.x] = W[(size_t)(f0 + threadIdx.y) * HH + h0 + threadIdx.x];
    __syncthreads();
    const float v = t[threadIdx.x][threadIdx.y];
    unsigned short hi, lo;
    split2(v, hi, lo);
    const size_t o = (size_t)(h0 + threadIdx.y) * FF + f0 + threadIdx.x;
    ((unsigned short*)th)[o] = hi;
    ((unsigned short*)tl)[o] = lo;
}

// ---------------- LSTM pointwise ----------------
__device__ __forceinline__ float sigm(float x) { return 1.0f / (1.0f + expf(-x)); }

__global__ void lstm_kernel(const float* __restrict__ gates,
                            const float* __restrict__ cprev,
                            bf16* __restrict__ hh, bf16* __restrict__ hl,
                            float* __restrict__ c, float* __restrict__ hf)
{
    const int idx = blockIdx.x * blockDim.x + threadIdx.x;
    const int n = idx >> 8;
    const int j4 = idx & 255;
    const float4* gp = (const float4*)(gates + (size_t)n * G4);
    const float4 gi = gp[j4];
    const float4 gf = gp[256 + j4];
    const float4 gg = gp[512 + j4];
    const float4 go = gp[768 + j4];
    float4 cp = make_float4(0.f, 0.f, 0.f, 0.f);
    if (cprev) cp = ((const float4*)cprev)[idx];
    float4 cn, hn;
    cn.x = sigm(gf.x) * cp.x + sigm(gi.x) * tanhf(gg.x);  hn.x = sigm(go.x) * tanhf(cn.x);
    cn.y = sigm(gf.y) * cp.y + sigm(gi.y) * tanhf(gg.y);  hn.y = sigm(go.y) * tanhf(cn.y);
    cn.z = sigm(gf.z) * cp.z + sigm(gi.z) * tanhf(gg.z);  hn.z = sigm(go.z) * tanhf(cn.z);
    cn.w = sigm(gf.w) * cp.w + sigm(gi.w) * tanhf(gg.w);  hn.w = sigm(go.w) * tanhf(cn.w);
    ((float4*)c)[idx] = cn;
    unsigned short h0, l0, h1, l1, h2, l2, h3, l3;
    split2(hn.x, h0, l0); split2(hn.y, h1, l1); split2(hn.z, h2, l2); split2(hn.w, h3, l3);
    ((ushort4*)hh)[idx] = make_ushort4(h0, h1, h2, h3);
    ((ushort4*)hl)[idx] = make_ushort4(l0, l1, l2, l3);
    if (hf) ((float4*)hf)[idx] = hn;
}

// ---------------- bias prep ----------------
__global__ void prep_kernel(const float* __restrict__ dWih, const float* __restrict__ bdc,
                            const float* __restrict__ dbih, const float* __restrict__ dbhh,
                            const float* __restrict__ ebih, const float* __restrict__ ebhh,
                            float* __restrict__ bdec0, float* __restrict__ bcomb,
                            float* __restrict__ benc)
{
    const int g = blockIdx.x;
    const int t = threadIdx.x;      // 128
    float p = 0.f;
    for (int k = t; k < FF; k += 128) p += dWih[(size_t)g * FF + k] * bdc[k];
    p += __shfl_down_sync(0xffffffffu, p, 16);
    p += __shfl_down_sync(0xffffffffu, p, 8);
    p += __shfl_down_sync(0xffffffffu, p, 4);
    p += __shfl_down_sync(0xffffffffu, p, 2);
    p += __shfl_down_sync(0xffffffffu, p, 1);
    __shared__ float sred[4];
    if ((t & 31) == 0) sred[t >> 5] = p;
    __syncthreads();
    if (t == 0) {
        const float srow = sred[0] + sred[1] + sred[2] + sred[3];
        const float b0 = dbih[g] + dbhh[g];
        bdec0[g] = b0;
        bcomb[g] = b0 + srow;
        benc[g]  = ebih[g] + ebhh[g];
    }
}

// ---------------- skinny head ----------------
__global__ void encscore_kernel(const float* __restrict__ h, const float* __restrict__ Wec,
                                const float* __restrict__ bec, float* __restrict__ out)
{
    const int warp = threadIdx.x >> 5;
    const int lane = threadIdx.x & 31;
    const int r = blockIdx.x * 8 + warp;
    float acc[CC];
#pragma unroll
    for (int n = 0; n < CC; n++) acc[n] = 0.f;
    const float* hr = h + (size_t)r * FF;
    for (int u = 0; u < FF / 32; u++) {
        const float hv = hr[u * 32 + lane];
#pragma unroll
        for (int n = 0; n < CC; n++) acc[n] += hv * Wec[n * FF + u * 32 + lane];
    }
#pragma unroll
    for (int n = 0; n < CC; n++) {
        float v = acc[n];
        v += __shfl_xor_sync(0xffffffffu, v, 16);
        v += __shfl_xor_sync(0xffffffffu, v, 8);
        v += __shfl_xor_sync(0xffffffffu, v, 4);
        v += __shfl_xor_sync(0xffffffffu, v, 2);
        v += __shfl_xor_sync(0xffffffffu, v, 1);
        if (lane == 0) out[(size_t)r * CC + n] = v + bec[n];
    }
}

// ---------------- launch ----------------
extern "C" void kernel_launch(void* const* d_in, const int* in_sizes, int n_in,
                              void* d_out, int out_size)
{
    const float* x    = (const float*)d_in[0];
    const float* Wf   = (const float*)d_in[1];
    const float* bf   = (const float*)d_in[2];
    const float* dWih = (const float*)d_in[3];
    const float* dWhh = (const float*)d_in[4];
    const float* dbih = (const float*)d_in[5];
    const float* dbhh = (const float*)d_in[6];
    const float* Wdc  = (const float*)d_in[7];
    const float* bdc  = (const float*)d_in[8];
    const float* eWih = (const float*)d_in[9];
    const float* eWhh = (const float*)d_in[10];
    const float* ebih = (const float*)d_in[11];
    const float* ebhh = (const float*)d_in[12];
    const float* Wec  = (const float*)d_in[13];
    const float* bec  = (const float*)d_in[14];

    float* enc_out = (float*)d_out;
    float* dec_out = (float*)d_out + (size_t)NROW * CC;

    unsigned char* ar = nullptr;
    cudaGetSymbolAddress((void**)&ar, g_arena);

    bf16* xh  = (bf16*)(ar + O_XH);   bf16* xl  = (bf16*)(ar + O_XL);
    bf16* Wfh = (bf16*)(ar + O_WFH);  bf16* Wfl = (bf16*)(ar + O_WFL);
    bf16* dih = (bf16*)(ar + O_DIH);  bf16* dil = (bf16*)(ar + O_DIL);
    bf16* eih = (bf16*)(ar + O_EIH);  bf16* eil = (bf16*)(ar + O_EIL);
    bf16* ehh = (bf16*)(ar + O_EHH);  bf16* ehl = (bf16*)(ar + O_EHL);
    bf16* wdh = (bf16*)(ar + O_WDH);  bf16* wdl = (bf16*)(ar + O_WDL);
    bf16* wth = (bf16*)(ar + O_WTH);  bf16* wtl = (bf16*)(ar + O_WTL);
    bf16* wch = (bf16*)(ar + O_WCH);  bf16* wcl = (bf16*)(ar + O_WCL);
    bf16* fh  = (bf16*)(ar + O_FH);   bf16* fl  = (bf16*)(ar + O_FL);
    bf16* hh  = (bf16*)(ar + O_HH);   bf16* hl  = (bf16*)(ar + O_HL);
    bf16* lh  = (bf16*)(ar + O_LH);   bf16* ll  = (bf16*)(ar + O_LL);
    float* cbuf  = (float*)(ar + O_C);
    float* gates = (float*)(ar + O_G);
    float* hfbuf = (float*)(ar + O_HF);
    float* bdec0 = (float*)(ar + O_B0);
    float* bcomb = (float*)(ar + O_B1);
    float* benc  = (float*)(ar + O_B2);

    cudaFuncSetAttribute(tcgemm, cudaFuncAttributeMaxDynamicSharedMemorySize, SMEM_DYN);

    // splits
    split_kernel<<<NROW * INN / 1024, 256>>>(x, xh, xl);
    split_kernel<<<FF * INN / 1024, 256>>>(Wf, Wfh, Wfl);
    split_kernel<<<G4 * FF / 1024, 256>>>(dWih, dih, dil);
    split_kernel<<<G4 * FF / 1024, 256>>>(eWih, eih, eil);
    split_kernel<<<G4 * FF / 1024, 256>>>(eWhh, ehh, ehl);
    split_kernel<<<FF * HH / 1024, 256>>>(Wdc, wdh, wdl);
    tsplit_kernel<<<dim3(HH / 32, FF / 32), dim3(32, 32)>>>(Wdc, wth, wtl);
    prep_kernel<<<G4, 128>>>(dWih, bdc, dbih, dbhh, ebih, ebhh, bdec0, bcomb, benc);

    const dim3 gBig(G4 / 128, NROW / 128);   // 32 x 32
    const dim3 gOut(FF / 128, NROW / 128);   // 8 x 32
    const int  lstmGrid = NROW * HH / 4 / 256;

    Passes P;

    // 1) feats = relu(x @ Wf^T + bf) -> split bf16 only
    P.A[0] = xh; P.B[0] = Wfh;  P.A[1] = xl; P.B[1] = Wfh;  P.A[2] = xh; P.B[2] = Wfl;
    tcgemm<<<gOut, 256, SMEM_DYN>>>(P, 3, INN, bf, nullptr, 0,
                                    nullptr, 0, fh, fl, FF, 1.0f, 1);

    // 2) Wcomb = dWih @ Wdc + dWhh  (B = WdcT split) -> split bf16
    P.A[0] = dih; P.B[0] = wth;  P.A[1] = dil; P.B[1] = wth;  P.A[2] = dih; P.B[2] = wtl;
    tcgemm<<<gOut, 256, SMEM_DYN>>>(P, 3, FF, nullptr, dWhh, HH,
                                    nullptr, 0, wch, wcl, HH, 1.0f, 0);

    // 3) decoder step 0: gates = feats @ dWih^T + bdec0
    P.A[0] = fh; P.B[0] = dih;  P.A[1] = fl; P.B[1] = dih;  P.A[2] = fh; P.B[2] = dil;
    tcgemm<<<gBig, 256, SMEM_DYN>>>(P, 3, FF, bdec0, nullptr, 0,
                                    gates, G4, nullptr, nullptr, 0, 1.0f, 0);
    lstm_kernel<<<lstmGrid, 256>>>(gates, nullptr, hh, hl, cbuf, nullptr);

    for (int t = 0; t < DD; t++) {
        // dec_out[:, t, :] = h @ Wdc^T + bdc ; last step also emits split(v/D)
        P.A[0] = hh; P.B[0] = wdh;  P.A[1] = hl; P.B[1] = wdh;  P.A[2] = hh; P.B[2] = wdl;
        const bool last = (t == DD - 1);
        tcgemm<<<gOut, 256, SMEM_DYN>>>(P, 3, HH, bdc, nullptr, 0,
                                        dec_out + (size_t)t * FF, DD * FF,
                                        last ? lh : nullptr, last ? ll : nullptr, FF,
                                        1.0f / (float)DD, 0);
        if (t + 1 < DD) {
            P.A[0] = hh; P.B[0] = wch;  P.A[1] = hl; P.B[1] = wch;  P.A[2] = hh; P.B[2] = wcl;
            tcgemm<<<gBig, 256, SMEM_DYN>>>(P, 3, HH, bcomb, nullptr, 0,
                                            gates, G4, nullptr, nullptr, 0, 1.0f, 0);
            lstm_kernel<<<lstmGrid, 256>>>(gates, cbuf, hh, hl, cbuf, nullptr);
        }
    }

    // encoder gates = feats @ eWih^T + (last/D) @ eWhh^T + benc  (6 passes)
    P.A[0] = fh; P.B[0] = eih;  P.A[1] = fl; P.B[1] = eih;  P.A[2] = fh; P.B[2] = eil;
    P.A[3] = lh; P.B[3] = ehh;  P.A[4] = ll; P.B[4] = ehh;  P.A[5] = lh; P.B[5] = ehl;
    tcgemm<<<gBig, 256, SMEM_DYN>>>(P, 6, FF, benc, nullptr, 0,
                                    gates, G4, nullptr, nullptr, 0, 1.0f, 0);
    lstm_kernel<<<lstmGrid, 256>>>(gates, nullptr, hh, hl, cbuf, hfbuf);

    encscore_kernel<<<NROW / 8, 256>>>(hfbuf, Wec, bec, enc_out);
}